// round 1
// baseline (speedup 1.0000x reference)
#include <cuda_runtime.h>

#define N_NODES 100000
#define N_EDGES 1000000
#define N_GRAPHS 128

// ---------------- scratch (static device globals; allocation-free) ----------
__device__ __align__(16) float g_aggr[N_NODES * 64];
__device__ __align__(16) float g_h1[N_NODES * 64];
__device__ __align__(16) float g_h2[N_NODES * 64];
__device__ __align__(16) float g_pool[N_GRAPHS * 64];

// ---------------- aggr = (1+eps) * x  (fused "self" term + buffer init) -----
__global__ __launch_bounds__(256) void k_init(const float4* __restrict__ x,
                                              const float* __restrict__ eps,
                                              float4* __restrict__ aggr) {
    int i = blockIdx.x * blockDim.x + threadIdx.x;   // over 100000*16 float4
    float s = 1.0f + *eps;
    float4 v = x[i];
    v.x *= s; v.y *= s; v.z *= s; v.w *= s;
    aggr[i] = v;
}

// ---------------- edge kernel: m = relu(x[src] + ea@We + be); aggr[dst]+=m --
// Tile: 64 edges x 64 cols per block of 256 threads.
// thread t: col group cg = t&15 (4 cols), edge group eg = t>>4 (4 edges).
__global__ __launch_bounds__(256) void k_edge(const float4* __restrict__ x4,
                                              const float* __restrict__ ea,
                                              const int* __restrict__ src,
                                              const int* __restrict__ dst,
                                              const float4* __restrict__ We4,
                                              const float4* __restrict__ be4,
                                              float4* __restrict__ aggr4) {
    __shared__ float  sEA[64][33];   // padded: avoid bank conflicts
    __shared__ float4 sW[32][16];    // We [32][64] as float4
    __shared__ float4 sBe[16];
    __shared__ int sSrc[64], sDst[64];

    const int tid = threadIdx.x;
    const int e0  = blockIdx.x * 64;

    for (int i = tid; i < 32 * 16; i += 256) sW[i >> 4][i & 15] = We4[i];
    if (tid < 16) sBe[tid] = be4[tid];
    if (tid < 64) { sSrc[tid] = src[e0 + tid]; sDst[tid] = dst[e0 + tid]; }
    for (int i = tid; i < 64 * 32; i += 256) {
        int e = i >> 5, k = i & 31;
        sEA[e][k] = ea[(size_t)(e0 + e) * 32 + k];
    }
    __syncthreads();

    const int cg = tid & 15;
    const int eg = tid >> 4;

    float4 acc[4];
#pragma unroll
    for (int i = 0; i < 4; i++) acc[i] = sBe[cg];

#pragma unroll
    for (int k = 0; k < 32; k++) {
        float4 w = sW[k][cg];
#pragma unroll
        for (int i = 0; i < 4; i++) {
            float a = sEA[eg * 4 + i][k];
            acc[i].x = fmaf(a, w.x, acc[i].x);
            acc[i].y = fmaf(a, w.y, acc[i].y);
            acc[i].z = fmaf(a, w.z, acc[i].z);
            acc[i].w = fmaf(a, w.w, acc[i].w);
        }
    }

#pragma unroll
    for (int i = 0; i < 4; i++) {
        int e = eg * 4 + i;
        int s = sSrc[e];
        int d = sDst[e];
        float4 xv = x4[(size_t)s * 16 + cg];
        float4 m;
        m.x = fmaxf(acc[i].x + xv.x, 0.0f);
        m.y = fmaxf(acc[i].y + xv.y, 0.0f);
        m.z = fmaxf(acc[i].z + xv.z, 0.0f);
        m.w = fmaxf(acc[i].w + xv.w, 0.0f);
        atomicAdd(&aggr4[(size_t)d * 16 + cg], m);  // sm_90+ vector RED
    }
}

// ---------------- node MLP: hout = relu( relu(hin@W1+b1) @ W2 + b2 ) --------
// Tile: 32 nodes per block of 256 threads.
// thread t: col group cg = t&15 (4 cols), node group ng = t>>4 (2 nodes).
__global__ __launch_bounds__(256) void k_mlp(const float* __restrict__ hin,
                                             const float4* __restrict__ W1_4,
                                             const float4* __restrict__ b1_4,
                                             const float4* __restrict__ W2_4,
                                             const float4* __restrict__ b2_4,
                                             float4* __restrict__ hout4) {
    __shared__ float4 sW1[64][16];
    __shared__ float4 sW2[64][16];
    __shared__ float  sH[32][65];
    __shared__ float  sT[32][65];
    __shared__ float4 sB1[16], sB2[16];

    const int tid = threadIdx.x;
    const int n0  = blockIdx.x * 32;

    for (int i = tid; i < 64 * 16; i += 256) {
        sW1[i >> 4][i & 15] = W1_4[i];
        sW2[i >> 4][i & 15] = W2_4[i];
    }
    if (tid < 16) { sB1[tid] = b1_4[tid]; sB2[tid] = b2_4[tid]; }
    for (int i = tid; i < 32 * 64; i += 256) {
        int n = i >> 6, k = i & 63;
        sH[n][k] = hin[(size_t)(n0 + n) * 64 + k];
    }
    __syncthreads();

    const int cg = tid & 15;
    const int ng = tid >> 4;
    const int na = ng * 2, nb = ng * 2 + 1;

    // layer 1
    float4 a0 = sB1[cg], a1 = sB1[cg];
#pragma unroll
    for (int k = 0; k < 64; k++) {
        float4 w = sW1[k][cg];
        float ha = sH[na][k];
        float hb = sH[nb][k];
        a0.x = fmaf(ha, w.x, a0.x); a0.y = fmaf(ha, w.y, a0.y);
        a0.z = fmaf(ha, w.z, a0.z); a0.w = fmaf(ha, w.w, a0.w);
        a1.x = fmaf(hb, w.x, a1.x); a1.y = fmaf(hb, w.y, a1.y);
        a1.z = fmaf(hb, w.z, a1.z); a1.w = fmaf(hb, w.w, a1.w);
    }
    sT[na][cg * 4 + 0] = fmaxf(a0.x, 0.0f);
    sT[na][cg * 4 + 1] = fmaxf(a0.y, 0.0f);
    sT[na][cg * 4 + 2] = fmaxf(a0.z, 0.0f);
    sT[na][cg * 4 + 3] = fmaxf(a0.w, 0.0f);
    sT[nb][cg * 4 + 0] = fmaxf(a1.x, 0.0f);
    sT[nb][cg * 4 + 1] = fmaxf(a1.y, 0.0f);
    sT[nb][cg * 4 + 2] = fmaxf(a1.z, 0.0f);
    sT[nb][cg * 4 + 3] = fmaxf(a1.w, 0.0f);
    __syncthreads();

    // layer 2 (+ outer relu of the conv)
    float4 c0 = sB2[cg], c1 = sB2[cg];
#pragma unroll
    for (int k = 0; k < 64; k++) {
        float4 w = sW2[k][cg];
        float ta = sT[na][k];
        float tb = sT[nb][k];
        c0.x = fmaf(ta, w.x, c0.x); c0.y = fmaf(ta, w.y, c0.y);
        c0.z = fmaf(ta, w.z, c0.z); c0.w = fmaf(ta, w.w, c0.w);
        c1.x = fmaf(tb, w.x, c1.x); c1.y = fmaf(tb, w.y, c1.y);
        c1.z = fmaf(tb, w.z, c1.z); c1.w = fmaf(tb, w.w, c1.w);
    }
    float4 o0, o1;
    o0.x = fmaxf(c0.x, 0.0f); o0.y = fmaxf(c0.y, 0.0f);
    o0.z = fmaxf(c0.z, 0.0f); o0.w = fmaxf(c0.w, 0.0f);
    o1.x = fmaxf(c1.x, 0.0f); o1.y = fmaxf(c1.y, 0.0f);
    o1.z = fmaxf(c1.z, 0.0f); o1.w = fmaxf(c1.w, 0.0f);
    hout4[(size_t)(n0 + na) * 16 + cg] = o0;
    hout4[(size_t)(n0 + nb) * 16 + cg] = o1;
}

// ---------------- pool: segment-sum over sorted batch (no atomics) ----------
__global__ __launch_bounds__(64) void k_pool(const float* __restrict__ h,
                                             const int* __restrict__ batch,
                                             float* __restrict__ pool) {
    const int g = blockIdx.x;
    const int c = threadIdx.x;
    int lo = 0, hi = N_NODES;
    while (lo < hi) { int mid = (lo + hi) >> 1; if (batch[mid] < g) lo = mid + 1; else hi = mid; }
    int start = lo;
    hi = N_NODES;
    while (lo < hi) { int mid = (lo + hi) >> 1; if (batch[mid] < g + 1) lo = mid + 1; else hi = mid; }
    int end = lo;
    float acc = 0.0f;
    for (int n = start; n < end; n++) acc += h[(size_t)n * 64 + c];
    pool[g * 64 + c] = acc;
}

// ---------------- head: out = relu(pool@Wf1+bf1) @ Wf2 + bf2 ----------------
__global__ __launch_bounds__(128) void k_head(const float* __restrict__ pool,
                                              const float* __restrict__ Wf1,
                                              const float* __restrict__ bf1,
                                              const float* __restrict__ Wf2,
                                              const float* __restrict__ bf2,
                                              float* __restrict__ out) {
    __shared__ float sW[64][128];
    const int tid = threadIdx.x;
    for (int i = tid; i < 64 * 128; i += 128) sW[i >> 7][i & 127] = Wf1[i];
    __syncthreads();

    float p[64];
#pragma unroll
    for (int k = 0; k < 64; k++) p[k] = pool[tid * 64 + k];

    float o = 0.0f;
    for (int j = 0; j < 128; j++) {
        float s = bf1[j];
#pragma unroll
        for (int k = 0; k < 64; k++) s = fmaf(p[k], sW[k][j], s);
        o = fmaf(fmaxf(s, 0.0f), Wf2[j], o);
    }
    out[tid] = o + bf2[0];
}

// ---------------- launch --------------------------------------------------
extern "C" void kernel_launch(void* const* d_in, const int* in_sizes, int n_in,
                              void* d_out, int out_size) {
    const float* x    = (const float*)d_in[0];
    const float* ea   = (const float*)d_in[1];
    const int*   src  = (const int*)d_in[2];
    const int*   dst  = (const int*)d_in[3];
    const int*   bat  = (const int*)d_in[4];
    const float* eps1 = (const float*)d_in[5];
    const float* We1  = (const float*)d_in[6];
    const float* be1  = (const float*)d_in[7];
    const float* W11  = (const float*)d_in[8];
    const float* b11  = (const float*)d_in[9];
    const float* W12  = (const float*)d_in[10];
    const float* b12  = (const float*)d_in[11];
    const float* eps2 = (const float*)d_in[12];
    const float* We2  = (const float*)d_in[13];
    const float* be2  = (const float*)d_in[14];
    const float* W21  = (const float*)d_in[15];
    const float* b21  = (const float*)d_in[16];
    const float* W22  = (const float*)d_in[17];
    const float* b22  = (const float*)d_in[18];
    const float* Wf1  = (const float*)d_in[19];
    const float* bf1  = (const float*)d_in[20];
    const float* Wf2  = (const float*)d_in[21];
    const float* bf2  = (const float*)d_in[22];

    void *aggr_p, *h1_p, *h2_p, *pool_p;
    cudaGetSymbolAddress(&aggr_p, g_aggr);
    cudaGetSymbolAddress(&h1_p, g_h1);
    cudaGetSymbolAddress(&h2_p, g_h2);
    cudaGetSymbolAddress(&pool_p, g_pool);
    float4* aggr4 = (float4*)aggr_p;
    float*  aggr  = (float*)aggr_p;
    float4* h1_4  = (float4*)h1_p;
    float*  h1    = (float*)h1_p;
    float4* h2_4  = (float4*)h2_p;
    float*  h2    = (float*)h2_p;
    float*  pool  = (float*)pool_p;

    const int INIT_BLOCKS = (N_NODES * 16) / 256;   // 6250
    const int EDGE_BLOCKS = N_EDGES / 64;           // 15625
    const int MLP_BLOCKS  = N_NODES / 32;           // 3125

    // ---- conv1 ----
    k_init<<<INIT_BLOCKS, 256>>>((const float4*)x, eps1, aggr4);
    k_edge<<<EDGE_BLOCKS, 256>>>((const float4*)x, ea, src, dst,
                                 (const float4*)We1, (const float4*)be1, aggr4);
    k_mlp<<<MLP_BLOCKS, 256>>>(aggr, (const float4*)W11, (const float4*)b11,
                               (const float4*)W12, (const float4*)b12, h1_4);
    // ---- conv2 ----
    k_init<<<INIT_BLOCKS, 256>>>((const float4*)h1, eps2, aggr4);
    k_edge<<<EDGE_BLOCKS, 256>>>((const float4*)h1, ea, src, dst,
                                 (const float4*)We2, (const float4*)be2, aggr4);
    k_mlp<<<MLP_BLOCKS, 256>>>(aggr, (const float4*)W21, (const float4*)b21,
                               (const float4*)W22, (const float4*)b22, h2_4);
    // ---- pool + head ----
    k_pool<<<N_GRAPHS, 64>>>(h2, bat, pool);
    k_head<<<1, 128>>>(pool, Wf1, bf1, Wf2, bf2, (float*)d_out);
}

// round 2
// speedup vs baseline: 1.1971x; 1.1971x over previous
#include <cuda_runtime.h>

#define N_NODES 100000
#define N_EDGES 1000000
#define N_GRAPHS 128

// ---------------- scratch (static device globals; allocation-free) ----------
__device__ __align__(16) float g_aggr[N_NODES * 64];
__device__ __align__(16) float g_h1[N_NODES * 64];
__device__ __align__(16) float g_pool[N_GRAPHS * 64];

// ---------------- aggr = (1+eps) * x  (fused "self" term + buffer init) -----
__global__ __launch_bounds__(256) void k_init(const float4* __restrict__ x,
                                              const float* __restrict__ eps,
                                              float4* __restrict__ aggr) {
    int i = blockIdx.x * blockDim.x + threadIdx.x;   // over 100000*16 float4
    float s = 1.0f + *eps;
    float4 v = x[i];
    v.x *= s; v.y *= s; v.z *= s; v.w *= s;
    aggr[i] = v;
}

// ---------------- edge kernel: m = relu(x[src] + ea@We + be); aggr[dst]+=m --
// Tile: 64 edges x 64 cols per block of 256 threads.
// thread t: col group cg = t&15 (4 cols), edge group eg = t>>4 (4 edges).
// Gathers for x[src] are issued FIRST so their L2 latency hides behind the
// smem staging + 2048-cycle FMA loop.
__global__ __launch_bounds__(256) void k_edge(const float4* __restrict__ x4,
                                              const float4* __restrict__ ea4,
                                              const int* __restrict__ src,
                                              const int* __restrict__ dst,
                                              const float4* __restrict__ We4,
                                              const float4* __restrict__ be4,
                                              float4* __restrict__ aggr4) {
    __shared__ float  sEA[64][33];   // padded: conflict-free reads
    __shared__ float4 sW[32][16];    // We [32][64] as float4
    __shared__ float4 sBe[16];
    __shared__ int sDst[64];

    const int tid = threadIdx.x;
    const int e0  = blockIdx.x * 64;
    const int cg  = tid & 15;
    const int eg  = tid >> 4;

    // ---- early gather: src ids then x rows (latency hidden behind FMA) ----
    int myS[4];
#pragma unroll
    for (int i = 0; i < 4; i++) myS[i] = __ldg(&src[e0 + eg * 4 + i]);
    float4 xv[4];
#pragma unroll
    for (int i = 0; i < 4; i++) xv[i] = __ldg(&x4[(size_t)myS[i] * 16 + cg]);

    // ---- stage weights / bias / edge attrs / dst ----
    for (int i = tid; i < 32 * 16; i += 256) sW[i >> 4][i & 15] = We4[i];
    if (tid < 16) sBe[tid] = be4[tid];
    if (tid < 64) sDst[tid] = dst[e0 + tid];
    // ea: 64 edges x 8 float4 = 512 vector loads, 2 per thread
#pragma unroll
    for (int i = tid; i < 512; i += 256) {
        int e = i >> 3, q = i & 7;
        float4 v = ea4[(size_t)(e0 + e) * 8 + q];
        sEA[e][q * 4 + 0] = v.x;
        sEA[e][q * 4 + 1] = v.y;
        sEA[e][q * 4 + 2] = v.z;
        sEA[e][q * 4 + 3] = v.w;
    }
    __syncthreads();

    float4 acc[4];
#pragma unroll
    for (int i = 0; i < 4; i++) acc[i] = sBe[cg];

#pragma unroll
    for (int k = 0; k < 32; k++) {
        float4 w = sW[k][cg];
#pragma unroll
        for (int i = 0; i < 4; i++) {
            float a = sEA[eg * 4 + i][k];
            acc[i].x = fmaf(a, w.x, acc[i].x);
            acc[i].y = fmaf(a, w.y, acc[i].y);
            acc[i].z = fmaf(a, w.z, acc[i].z);
            acc[i].w = fmaf(a, w.w, acc[i].w);
        }
    }

#pragma unroll
    for (int i = 0; i < 4; i++) {
        int d = sDst[eg * 4 + i];
        float4 m;
        m.x = fmaxf(acc[i].x + xv[i].x, 0.0f);
        m.y = fmaxf(acc[i].y + xv[i].y, 0.0f);
        m.z = fmaxf(acc[i].z + xv[i].z, 0.0f);
        m.w = fmaxf(acc[i].w + xv[i].w, 0.0f);
        atomicAdd(&aggr4[(size_t)d * 16 + cg], m);  // RED.E.128, fire-and-forget
    }
}

// ---------------- node MLP: hout = relu( relu(hin@W1+b1) @ W2 + b2 ) --------
// Tile: 32 nodes per block of 256 threads.
// POOL variant: instead of writing hout, atomically add into pool[batch[n]].
template <bool POOL>
__global__ __launch_bounds__(256) void k_mlp(const float* __restrict__ hin,
                                             const float4* __restrict__ W1_4,
                                             const float4* __restrict__ b1_4,
                                             const float4* __restrict__ W2_4,
                                             const float4* __restrict__ b2_4,
                                             float4* __restrict__ hout4,
                                             const int* __restrict__ batch,
                                             float4* __restrict__ pool4) {
    __shared__ float4 sW1[64][16];
    __shared__ float4 sW2[64][16];
    __shared__ float  sH[32][65];
    __shared__ float  sT[32][65];
    __shared__ float4 sB1[16], sB2[16];
    __shared__ int    sBatch[32];

    const int tid = threadIdx.x;
    const int n0  = blockIdx.x * 32;

    for (int i = tid; i < 64 * 16; i += 256) {
        sW1[i >> 4][i & 15] = W1_4[i];
        sW2[i >> 4][i & 15] = W2_4[i];
    }
    if (tid < 16) { sB1[tid] = b1_4[tid]; sB2[tid] = b2_4[tid]; }
    if (POOL && tid < 32) sBatch[tid] = batch[n0 + tid];
    for (int i = tid; i < 32 * 64; i += 256) {
        int n = i >> 6, k = i & 63;
        sH[n][k] = hin[(size_t)(n0 + n) * 64 + k];
    }
    __syncthreads();

    const int cg = tid & 15;
    const int ng = tid >> 4;
    const int na = ng * 2, nb = ng * 2 + 1;

    // layer 1
    float4 a0 = sB1[cg], a1 = sB1[cg];
#pragma unroll
    for (int k = 0; k < 64; k++) {
        float4 w = sW1[k][cg];
        float ha = sH[na][k];
        float hb = sH[nb][k];
        a0.x = fmaf(ha, w.x, a0.x); a0.y = fmaf(ha, w.y, a0.y);
        a0.z = fmaf(ha, w.z, a0.z); a0.w = fmaf(ha, w.w, a0.w);
        a1.x = fmaf(hb, w.x, a1.x); a1.y = fmaf(hb, w.y, a1.y);
        a1.z = fmaf(hb, w.z, a1.z); a1.w = fmaf(hb, w.w, a1.w);
    }
    sT[na][cg * 4 + 0] = fmaxf(a0.x, 0.0f);
    sT[na][cg * 4 + 1] = fmaxf(a0.y, 0.0f);
    sT[na][cg * 4 + 2] = fmaxf(a0.z, 0.0f);
    sT[na][cg * 4 + 3] = fmaxf(a0.w, 0.0f);
    sT[nb][cg * 4 + 0] = fmaxf(a1.x, 0.0f);
    sT[nb][cg * 4 + 1] = fmaxf(a1.y, 0.0f);
    sT[nb][cg * 4 + 2] = fmaxf(a1.z, 0.0f);
    sT[nb][cg * 4 + 3] = fmaxf(a1.w, 0.0f);
    __syncthreads();

    // layer 2 (+ outer relu of the conv)
    float4 c0 = sB2[cg], c1 = sB2[cg];
#pragma unroll
    for (int k = 0; k < 64; k++) {
        float4 w = sW2[k][cg];
        float ta = sT[na][k];
        float tb = sT[nb][k];
        c0.x = fmaf(ta, w.x, c0.x); c0.y = fmaf(ta, w.y, c0.y);
        c0.z = fmaf(ta, w.z, c0.z); c0.w = fmaf(ta, w.w, c0.w);
        c1.x = fmaf(tb, w.x, c1.x); c1.y = fmaf(tb, w.y, c1.y);
        c1.z = fmaf(tb, w.z, c1.z); c1.w = fmaf(tb, w.w, c1.w);
    }
    float4 o0, o1;
    o0.x = fmaxf(c0.x, 0.0f); o0.y = fmaxf(c0.y, 0.0f);
    o0.z = fmaxf(c0.z, 0.0f); o0.w = fmaxf(c0.w, 0.0f);
    o1.x = fmaxf(c1.x, 0.0f); o1.y = fmaxf(c1.y, 0.0f);
    o1.z = fmaxf(c1.z, 0.0f); o1.w = fmaxf(c1.w, 0.0f);

    if (POOL) {
        atomicAdd(&pool4[(size_t)sBatch[na] * 16 + cg], o0);
        atomicAdd(&pool4[(size_t)sBatch[nb] * 16 + cg], o1);
    } else {
        hout4[(size_t)(n0 + na) * 16 + cg] = o0;
        hout4[(size_t)(n0 + nb) * 16 + cg] = o1;
    }
}

// ---------------- head: out = relu(pool@Wf1+bf1) @ Wf2 + bf2 ----------------
__global__ __launch_bounds__(128) void k_head(const float* __restrict__ pool,
                                              const float* __restrict__ Wf1,
                                              const float* __restrict__ bf1,
                                              const float* __restrict__ Wf2,
                                              const float* __restrict__ bf2,
                                              float* __restrict__ out) {
    __shared__ float sW[64][128];
    const int tid = threadIdx.x;
    for (int i = tid; i < 64 * 128; i += 128) sW[i >> 7][i & 127] = Wf1[i];
    __syncthreads();

    float p[64];
#pragma unroll
    for (int k = 0; k < 64; k++) p[k] = pool[tid * 64 + k];

    float o = 0.0f;
    for (int j = 0; j < 128; j++) {
        float s = bf1[j];
#pragma unroll
        for (int k = 0; k < 64; k++) s = fmaf(p[k], sW[k][j], s);
        o = fmaf(fmaxf(s, 0.0f), Wf2[j], o);
    }
    out[tid] = o + bf2[0];
}

// ---------------- launch --------------------------------------------------
extern "C" void kernel_launch(void* const* d_in, const int* in_sizes, int n_in,
                              void* d_out, int out_size) {
    const float* x    = (const float*)d_in[0];
    const float* ea   = (const float*)d_in[1];
    const int*   src  = (const int*)d_in[2];
    const int*   dst  = (const int*)d_in[3];
    const int*   bat  = (const int*)d_in[4];
    const float* eps1 = (const float*)d_in[5];
    const float* We1  = (const float*)d_in[6];
    const float* be1  = (const float*)d_in[7];
    const float* W11  = (const float*)d_in[8];
    const float* b11  = (const float*)d_in[9];
    const float* W12  = (const float*)d_in[10];
    const float* b12  = (const float*)d_in[11];
    const float* eps2 = (const float*)d_in[12];
    const float* We2  = (const float*)d_in[13];
    const float* be2  = (const float*)d_in[14];
    const float* W21  = (const float*)d_in[15];
    const float* b21  = (const float*)d_in[16];
    const float* W22  = (const float*)d_in[17];
    const float* b22  = (const float*)d_in[18];
    const float* Wf1  = (const float*)d_in[19];
    const float* bf1  = (const float*)d_in[20];
    const float* Wf2  = (const float*)d_in[21];
    const float* bf2  = (const float*)d_in[22];

    void *aggr_p, *h1_p, *pool_p;
    cudaGetSymbolAddress(&aggr_p, g_aggr);
    cudaGetSymbolAddress(&h1_p, g_h1);
    cudaGetSymbolAddress(&pool_p, g_pool);
    float4* aggr4 = (float4*)aggr_p;
    float*  aggr  = (float*)aggr_p;
    float4* h1_4  = (float4*)h1_p;
    float*  h1    = (float*)h1_p;
    float4* pool4 = (float4*)pool_p;
    float*  pool  = (float*)pool_p;

    const int INIT_BLOCKS = (N_NODES * 16) / 256;   // 6250
    const int EDGE_BLOCKS = N_EDGES / 64;           // 15625
    const int MLP_BLOCKS  = N_NODES / 32;           // 3125

    // zero pool accumulator (graph-capturable memset node)
    cudaMemsetAsync(pool_p, 0, N_GRAPHS * 64 * sizeof(float));

    // ---- conv1 ----
    k_init<<<INIT_BLOCKS, 256>>>((const float4*)x, eps1, aggr4);
    k_edge<<<EDGE_BLOCKS, 256>>>((const float4*)x, (const float4*)ea, src, dst,
                                 (const float4*)We1, (const float4*)be1, aggr4);
    k_mlp<false><<<MLP_BLOCKS, 256>>>(aggr, (const float4*)W11, (const float4*)b11,
                                      (const float4*)W12, (const float4*)b12,
                                      h1_4, nullptr, nullptr);
    // ---- conv2 ----
    k_init<<<INIT_BLOCKS, 256>>>((const float4*)h1, eps2, aggr4);
    k_edge<<<EDGE_BLOCKS, 256>>>((const float4*)h1, (const float4*)ea, src, dst,
                                 (const float4*)We2, (const float4*)be2, aggr4);
    k_mlp<true><<<MLP_BLOCKS, 256>>>(aggr, (const float4*)W21, (const float4*)b21,
                                     (const float4*)W22, (const float4*)b22,
                                     nullptr, bat, pool4);
    // ---- head ----
    k_head<<<1, 128>>>(pool, Wf1, bf1, Wf2, bf2, (float*)d_out);
}